// round 3
// baseline (speedup 1.0000x reference)
#include <cuda_runtime.h>
#include <math.h>

// Problem constants
#define B_  4
#define N_  1024
#define M_  2048
#define D_  1024
#define H_  16
#define HD_ 64
#define P_  64

// ---------------------------------------------------------------------------
// Scratch: one big __device__ global, offsets in floats
// ---------------------------------------------------------------------------
#define OFF_QIN   0ull
#define OFF_KVIN  (OFF_QIN  + 4096ull*1024)
#define OFF_Q     (OFF_KVIN + 8192ull*1024)
#define OFF_K     (OFF_Q    + 4096ull*1024)
#define OFF_V     (OFF_K    + 8192ull*1024)
#define OFF_GEOQ  (OFF_V    + 8192ull*1024)
#define OFF_GEOK  (OFF_GEOQ + 4096ull*64)
#define OFF_BIAS  (OFF_GEOK + 8192ull*64)
#define OFF_ATTN  (OFF_BIAS + 4ull*1024*2048)
#define OFF_OUT1  (OFF_ATTN + 4096ull*1024)
#define OFF_HLN   (OFF_OUT1 + 4096ull*1024)
#define OFF_FF1   (OFF_HLN  + 4096ull*1024)
#define SCRATCH_FLOATS (OFF_FF1 + 4096ull*2048)

__device__ float g_scratch[SCRATCH_FLOATS];

// ---------------------------------------------------------------------------
// LayerNorm over D=1024, one block (256 threads) per row, float4 everything.
// ---------------------------------------------------------------------------
__global__ void layernorm_kernel(const float* __restrict__ x,
                                 const float* __restrict__ g,
                                 const float* __restrict__ bta,
                                 float* __restrict__ y)
{
    int row = blockIdx.x;
    int t = threadIdx.x;
    float4 v = reinterpret_cast<const float4*>(x + (size_t)row * D_)[t];
    float s  = v.x + v.y + v.z + v.w;
    float ss = v.x*v.x + v.y*v.y + v.z*v.z + v.w*v.w;

    __shared__ float sh[16];
    int lane = t & 31, wid = t >> 5;
    #pragma unroll
    for (int o = 16; o; o >>= 1) {
        s  += __shfl_xor_sync(0xffffffffu, s,  o);
        ss += __shfl_xor_sync(0xffffffffu, ss, o);
    }
    if (lane == 0) { sh[wid] = s; sh[8 + wid] = ss; }
    __syncthreads();
    if (t < 32) {
        s  = (t < 8) ? sh[t]     : 0.f;
        ss = (t < 8) ? sh[8 + t] : 0.f;
        #pragma unroll
        for (int o = 4; o; o >>= 1) {
            s  += __shfl_xor_sync(0xffffffffu, s,  o);
            ss += __shfl_xor_sync(0xffffffffu, ss, o);
        }
        if (t == 0) { sh[0] = s; sh[8] = ss; }
    }
    __syncthreads();
    float mean = sh[0] * (1.f / D_);
    float var  = sh[8] * (1.f / D_) - mean * mean;
    float rstd = rsqrtf(var + 1e-5f);

    float4 gv = reinterpret_cast<const float4*>(g)[t];
    float4 bv = reinterpret_cast<const float4*>(bta)[t];
    float4 o;
    o.x = (v.x - mean) * rstd * gv.x + bv.x;
    o.y = (v.y - mean) * rstd * gv.y + bv.y;
    o.z = (v.z - mean) * rstd * gv.z + bv.z;
    o.w = (v.w - mean) * rstd * gv.w + bv.w;
    reinterpret_cast<float4*>(y + (size_t)row * D_)[t] = o;
}

// ---------------------------------------------------------------------------
// L2 normalize over the sequence axis: x[B, Nn, 64]; one block per (b, p).
// ---------------------------------------------------------------------------
__global__ void l2norm_kernel(float* __restrict__ x, int Nn)
{
    int b = blockIdx.x >> 6;
    int p = blockIdx.x & 63;
    float* base = x + (size_t)b * Nn * P_ + p;
    int t = threadIdx.x;

    float ss = 0.f;
    for (int n = t; n < Nn; n += 256) {
        float v = base[(size_t)n * P_];
        ss += v * v;
    }
    __shared__ float sh[9];
    int lane = t & 31, wid = t >> 5;
    #pragma unroll
    for (int o = 16; o; o >>= 1) ss += __shfl_xor_sync(0xffffffffu, ss, o);
    if (lane == 0) sh[wid] = ss;
    __syncthreads();
    if (t == 0) {
        float tot = 0.f;
        #pragma unroll
        for (int i = 0; i < 8; i++) tot += sh[i];
        sh[8] = 1.f / fmaxf(sqrtf(tot), 1e-12f);
    }
    __syncthreads();
    float inv = sh[8];
    for (int n = t; n < Nn; n += 256) base[(size_t)n * P_] *= inv;
}

// ---------------------------------------------------------------------------
// SGEMM: C[Mr,Nc] = A[Mr,K] @ W[K,Nc] + bias, with epilogue variants.
// 128x128x8 tiles, 256 threads, 8x8 per thread. Mr%128==0, K%8==0 assumed.
// EPI: 0 = +bias, 1 = +bias + residual R, 2 = +bias then exact GELU.
// ---------------------------------------------------------------------------
#define GBM 128
#define GBN 128
#define GBK 8
#define GTM 8
#define GTN 8

template<int EPI>
__global__ void sgemm_kernel(const float* __restrict__ A, const float* __restrict__ W,
                             const float* __restrict__ bias, const float* __restrict__ R,
                             float* __restrict__ C, int Mr, int Nc, int K)
{
    __shared__ float As[GBK][GBM];
    __shared__ float Bs[GBK][GBN];

    int tid  = threadIdx.x;
    int row0 = blockIdx.y * GBM;
    int col0 = blockIdx.x * GBN;

    int a_row = tid >> 1;            // 0..127
    int a_col = (tid & 1) * 4;       // 0 or 4
    int b_row = tid >> 5;            // 0..7
    int b_col = (tid & 31) * 4;      // 0..124
    int ty = tid >> 4, tx = tid & 15;

    float acc[GTM][GTN] = {};

    for (int k0 = 0; k0 < K; k0 += GBK) {
        float4 av = *reinterpret_cast<const float4*>(
            &A[(size_t)(row0 + a_row) * K + k0 + a_col]);
        As[a_col + 0][a_row] = av.x;
        As[a_col + 1][a_row] = av.y;
        As[a_col + 2][a_row] = av.z;
        As[a_col + 3][a_row] = av.w;

        float4 bv = make_float4(0.f, 0.f, 0.f, 0.f);
        if (col0 + b_col < Nc)
            bv = *reinterpret_cast<const float4*>(
                &W[(size_t)(k0 + b_row) * Nc + col0 + b_col]);
        *reinterpret_cast<float4*>(&Bs[b_row][b_col]) = bv;
        __syncthreads();

        #pragma unroll
        for (int k = 0; k < GBK; k++) {
            float ar[GTM], br[GTN];
            #pragma unroll
            for (int i = 0; i < GTM; i++) ar[i] = As[k][ty * GTM + i];
            #pragma unroll
            for (int j = 0; j < GTN; j++) br[j] = Bs[k][tx * GTN + j];
            #pragma unroll
            for (int i = 0; i < GTM; i++)
                #pragma unroll
                for (int j = 0; j < GTN; j++)
                    acc[i][j] += ar[i] * br[j];
        }
        __syncthreads();
    }

    #pragma unroll
    for (int i = 0; i < GTM; i++) {
        int rr = row0 + ty * GTM + i;
        #pragma unroll
        for (int j = 0; j < GTN; j++) {
            int cc = col0 + tx * GTN + j;
            if (cc < Nc) {
                float v = acc[i][j] + bias[cc];
                if (EPI == 1) v += R[(size_t)rr * Nc + cc];
                else if (EPI == 2) v = 0.5f * v * (1.f + erff(v * 0.70710678118654752f));
                C[(size_t)rr * Nc + cc] = v;
            }
        }
    }
}

// ---------------------------------------------------------------------------
// Geo bias: bias[b,n,m] = f(geo_q[b,n,:] . geo_k[b,m,:]), f = relu*pos - relu(-)*neg
// 64x64 output tile, K=64 in smem, 256 threads, 4x4 per thread.
// ---------------------------------------------------------------------------
__global__ void bias_nt_kernel(const float* __restrict__ gq, const float* __restrict__ gk,
                               const float* __restrict__ pos, const float* __restrict__ neg,
                               float* __restrict__ Cb)
{
    __shared__ float Aq[64 * 68];
    __shared__ float Bk[64 * 68];
    int tid = threadIdx.x;
    int m0 = blockIdx.x * 64, n0 = blockIdx.y * 64, b = blockIdx.z;

    #pragma unroll
    for (int it = 0; it < 4; it++) {
        int idx = tid + it * 256;
        int row = idx >> 4;
        int c4  = (idx & 15) * 4;
        *reinterpret_cast<float4*>(&Aq[row * 68 + c4]) =
            *reinterpret_cast<const float4*>(&gq[((size_t)(b * N_ + n0 + row)) * P_ + c4]);
        *reinterpret_cast<float4*>(&Bk[row * 68 + c4]) =
            *reinterpret_cast<const float4*>(&gk[((size_t)(b * M_ + m0 + row)) * P_ + c4]);
    }
    __syncthreads();

    int ty = tid >> 4, tx = tid & 15;
    float acc[4][4] = {};
    #pragma unroll
    for (int k = 0; k < 64; k += 4) {
        float4 a[4], kb[4];
        #pragma unroll
        for (int i = 0; i < 4; i++) a[i]  = *reinterpret_cast<float4*>(&Aq[(ty*4 + i)*68 + k]);
        #pragma unroll
        for (int j = 0; j < 4; j++) kb[j] = *reinterpret_cast<float4*>(&Bk[(tx*4 + j)*68 + k]);
        #pragma unroll
        for (int i = 0; i < 4; i++)
            #pragma unroll
            for (int j = 0; j < 4; j++)
                acc[i][j] += a[i].x*kb[j].x + a[i].y*kb[j].y + a[i].z*kb[j].z + a[i].w*kb[j].w;
    }

    float ps = pos[0], ns = neg[0];
    #pragma unroll
    for (int i = 0; i < 4; i++) {
        float4 o;
        o.x = acc[i][0] > 0.f ? acc[i][0] * ps : acc[i][0] * ns;
        o.y = acc[i][1] > 0.f ? acc[i][1] * ps : acc[i][1] * ns;
        o.z = acc[i][2] > 0.f ? acc[i][2] * ps : acc[i][2] * ns;
        o.w = acc[i][3] > 0.f ? acc[i][3] * ps : acc[i][3] * ns;
        *reinterpret_cast<float4*>(
            &Cb[((size_t)(b * N_ + n0 + ty*4 + i)) * M_ + m0 + tx*4]) = o;
    }
}

// ---------------------------------------------------------------------------
// Flash attention with additive bias (shared across heads).
// Block: 256 threads; tile: 64 queries x full HD=64; M streamed in 64-chunks.
// Smem arrays padded to stride 68 floats (keeps float4 LDS conflict-free).
// ---------------------------------------------------------------------------
#define FL_STRIDE 68
#define FLASH_SMEM (4 * 64 * FL_STRIDE * 4)

__global__ void flash_attn_kernel(const float* __restrict__ Q, const float* __restrict__ K,
                                  const float* __restrict__ V, const float* __restrict__ Bias,
                                  const float* __restrict__ logit_scale,
                                  float* __restrict__ O)
{
    extern __shared__ float sm[];
    float* Qs = sm;
    float* Ks = Qs + 64 * FL_STRIDE;
    float* Vs = Ks + 64 * FL_STRIDE;
    float* Ps = Vs + 64 * FL_STRIDE;

    const int tid = threadIdx.x;
    const int n0 = blockIdx.x * 64;
    const int h  = blockIdx.y;
    const int b  = blockIdx.z;
    const float scale = __expf(logit_scale[0]) * 0.125f;  // exp(ls)/sqrt(64)

    // Load + pre-scale Q tile
    #pragma unroll
    for (int it = 0; it < 4; it++) {
        int idx = tid + it * 256;
        int row = idx >> 4;
        int c4  = (idx & 15) * 4;
        float4 v = *reinterpret_cast<const float4*>(
            &Q[((size_t)(b * N_ + n0 + row)) * D_ + h * HD_ + c4]);
        v.x *= scale; v.y *= scale; v.z *= scale; v.w *= scale;
        *reinterpret_cast<float4*>(&Qs[row * FL_STRIDE + c4]) = v;
    }

    const int r  = tid >> 2;   // softmax/output row ownership
    const int cg = tid & 3;    // 4 lanes cooperate per row
    const int ty = tid >> 4, tx = tid & 15;  // S-compute mapping

    float Oacc[16] = {};
    float m_i = -1e30f, l_i = 0.f;

    for (int m0 = 0; m0 < M_; m0 += 64) {
        __syncthreads();  // previous iteration's consumers of Ks/Vs/Ps done
        #pragma unroll
        for (int it = 0; it < 4; it++) {
            int idx = tid + it * 256;
            int row = idx >> 4;
            int c4  = (idx & 15) * 4;
            size_t gbase = ((size_t)(b * M_ + m0 + row)) * D_ + h * HD_ + c4;
            *reinterpret_cast<float4*>(&Ks[row * FL_STRIDE + c4]) =
                *reinterpret_cast<const float4*>(&K[gbase]);
            *reinterpret_cast<float4*>(&Vs[row * FL_STRIDE + c4]) =
                *reinterpret_cast<const float4*>(&V[gbase]);
        }
        __syncthreads();

        // S = Qs @ Ks^T  (4x4 per thread) + bias
        float acc[4][4] = {};
        #pragma unroll
        for (int k = 0; k < 64; k += 4) {
            float4 qa[4], kb[4];
            #pragma unroll
            for (int i = 0; i < 4; i++) qa[i] = *reinterpret_cast<float4*>(&Qs[(ty*4+i)*FL_STRIDE + k]);
            #pragma unroll
            for (int j = 0; j < 4; j++) kb[j] = *reinterpret_cast<float4*>(&Ks[(tx*4+j)*FL_STRIDE + k]);
            #pragma unroll
            for (int i = 0; i < 4; i++)
                #pragma unroll
                for (int j = 0; j < 4; j++)
                    acc[i][j] += qa[i].x*kb[j].x + qa[i].y*kb[j].y +
                                 qa[i].z*kb[j].z + qa[i].w*kb[j].w;
        }
        #pragma unroll
        for (int i = 0; i < 4; i++) {
            float4 bv = *reinterpret_cast<const float4*>(
                &Bias[((size_t)(b * N_ + n0 + ty*4 + i)) * M_ + m0 + tx*4]);
            float* prow = &Ps[(ty*4 + i) * FL_STRIDE + tx*4];
            prow[0] = acc[i][0] + bv.x;
            prow[1] = acc[i][1] + bv.y;
            prow[2] = acc[i][2] + bv.z;
            prow[3] = acc[i][3] + bv.w;
        }
        __syncthreads();

        // Online softmax: row r, 16 cols per thread, 4-lane shfl reductions
        float s[16];
        float cmax = -1e30f;
        #pragma unroll
        for (int jj = 0; jj < 16; jj++) {
            s[jj] = Ps[r * FL_STRIDE + cg * 16 + jj];
            cmax = fmaxf(cmax, s[jj]);
        }
        cmax = fmaxf(cmax, __shfl_xor_sync(0xffffffffu, cmax, 1));
        cmax = fmaxf(cmax, __shfl_xor_sync(0xffffffffu, cmax, 2));
        float m_new = fmaxf(m_i, cmax);
        float alpha = __expf(m_i - m_new);
        float lsum = 0.f;
        #pragma unroll
        for (int jj = 0; jj < 16; jj++) {
            float p = __expf(s[jj] - m_new);
            Ps[r * FL_STRIDE + cg * 16 + jj] = p;
            lsum += p;
        }
        lsum += __shfl_xor_sync(0xffffffffu, lsum, 1);
        lsum += __shfl_xor_sync(0xffffffffu, lsum, 2);
        l_i = l_i * alpha + lsum;
        m_i = m_new;
        __syncthreads();

        // O[r][d] update, d = cg*16 + dd
        #pragma unroll
        for (int dd = 0; dd < 16; dd++) Oacc[dd] *= alpha;
        #pragma unroll 4
        for (int j = 0; j < 64; j++) {
            float p = Ps[r * FL_STRIDE + j];
            const float* vrow = &Vs[j * FL_STRIDE + cg * 16];
            float4 v0 = *reinterpret_cast<const float4*>(vrow + 0);
            float4 v1 = *reinterpret_cast<const float4*>(vrow + 4);
            float4 v2 = *reinterpret_cast<const float4*>(vrow + 8);
            float4 v3 = *reinterpret_cast<const float4*>(vrow + 12);
            Oacc[0]  += p * v0.x; Oacc[1]  += p * v0.y; Oacc[2]  += p * v0.z; Oacc[3]  += p * v0.w;
            Oacc[4]  += p * v1.x; Oacc[5]  += p * v1.y; Oacc[6]  += p * v1.z; Oacc[7]  += p * v1.w;
            Oacc[8]  += p * v2.x; Oacc[9]  += p * v2.y; Oacc[10] += p * v2.z; Oacc[11] += p * v2.w;
            Oacc[12] += p * v3.x; Oacc[13] += p * v3.y; Oacc[14] += p * v3.z; Oacc[15] += p * v3.w;
        }
    }

    float inv = 1.f / l_i;
    size_t obase = ((size_t)(b * N_ + n0 + r)) * D_ + h * HD_ + cg * 16;
    #pragma unroll
    for (int dd = 0; dd < 16; dd += 4) {
        float4 o;
        o.x = Oacc[dd + 0] * inv;
        o.y = Oacc[dd + 1] * inv;
        o.z = Oacc[dd + 2] * inv;
        o.w = Oacc[dd + 3] * inv;
        *reinterpret_cast<float4*>(&O[obase + dd]) = o;
    }
}

// ---------------------------------------------------------------------------
// Launcher
// ---------------------------------------------------------------------------
extern "C" void kernel_launch(void* const* d_in, const int* in_sizes, int n_in,
                              void* d_out, int out_size)
{
    const float* dataset  = (const float*)d_in[0];
    const float* visual   = (const float*)d_in[1];
    const float* wq_w     = (const float*)d_in[2];
    const float* wq_b     = (const float*)d_in[3];
    const float* wk_w     = (const float*)d_in[4];
    const float* wk_b     = (const float*)d_in[5];
    const float* wv_w     = (const float*)d_in[6];
    const float* wv_b     = (const float*)d_in[7];
    const float* wo_w     = (const float*)d_in[8];
    const float* wo_b     = (const float*)d_in[9];
    const float* gq_w     = (const float*)d_in[10];
    const float* gq_b     = (const float*)d_in[11];
    const float* gk_w     = (const float*)d_in[12];
    const float* gk_b     = (const float*)d_in[13];
    const float* pos_s    = (const float*)d_in[14];
    const float* neg_s    = (const float*)d_in[15];
    const float* attn_ls  = (const float*)d_in[16];
    const float* ln_q_g   = (const float*)d_in[17];
    const float* ln_q_b   = (const float*)d_in[18];
    const float* ln_kv_g  = (const float*)d_in[19];
    const float* ln_kv_b  = (const float*)d_in[20];
    const float* ln_out_g = (const float*)d_in[21];
    const float* ln_out_b = (const float*)d_in[22];
    const float* ff1_w    = (const float*)d_in[23];
    const float* ff1_b    = (const float*)d_in[24];
    const float* ff2_w    = (const float*)d_in[25];
    const float* ff2_b    = (const float*)d_in[26];
    float* out = (float*)d_out;

    float* sc = nullptr;
    cudaGetSymbolAddress((void**)&sc, g_scratch);
    float* q_in  = sc + OFF_QIN;
    float* kv_in = sc + OFF_KVIN;
    float* Qp    = sc + OFF_Q;
    float* Kp    = sc + OFF_K;
    float* Vp    = sc + OFF_V;
    float* geoq  = sc + OFF_GEOQ;
    float* geok  = sc + OFF_GEOK;
    float* biasb = sc + OFF_BIAS;
    float* attnb = sc + OFF_ATTN;
    float* out1  = sc + OFF_OUT1;
    float* hln   = sc + OFF_HLN;
    float* ff1   = sc + OFF_FF1;

    dim3 blk(256);

    // 1-2: LayerNorms
    layernorm_kernel<<<4096, blk>>>(dataset, ln_q_g, ln_q_b, q_in);
    layernorm_kernel<<<8192, blk>>>(visual, ln_kv_g, ln_kv_b, kv_in);

    // 3-4: geo projections (N=64)
    sgemm_kernel<0><<<dim3(1, 32), blk>>>(q_in,  gq_w, gq_b, nullptr, geoq, 4096, 64, 1024);
    sgemm_kernel<0><<<dim3(1, 64), blk>>>(kv_in, gk_w, gk_b, nullptr, geok, 8192, 64, 1024);

    // 5-6: L2 normalize over sequence axis
    l2norm_kernel<<<256, blk>>>(geoq, N_);
    l2norm_kernel<<<256, blk>>>(geok, M_);

    // 7: geo bias [B,N,M]
    bias_nt_kernel<<<dim3(32, 16, 4), blk>>>(geoq, geok, pos_s, neg_s, biasb);

    // 8-10: QKV projections
    sgemm_kernel<0><<<dim3(8, 32), blk>>>(q_in,  wq_w, wq_b, nullptr, Qp, 4096, 1024, 1024);
    sgemm_kernel<0><<<dim3(8, 64), blk>>>(kv_in, wk_w, wk_b, nullptr, Kp, 8192, 1024, 1024);
    sgemm_kernel<0><<<dim3(8, 64), blk>>>(kv_in, wv_w, wv_b, nullptr, Vp, 8192, 1024, 1024);

    // 11: flash attention with bias
    cudaFuncSetAttribute(flash_attn_kernel,
                         cudaFuncAttributeMaxDynamicSharedMemorySize, FLASH_SMEM);
    flash_attn_kernel<<<dim3(16, 16, 4), blk, FLASH_SMEM>>>(Qp, Kp, Vp, biasb, attn_ls, attnb);

    // 12: output projection + residual
    sgemm_kernel<1><<<dim3(8, 32), blk>>>(attnb, wo_w, wo_b, dataset, out1, 4096, 1024, 1024);

    // 13: post-LN
    layernorm_kernel<<<4096, blk>>>(out1, ln_out_g, ln_out_b, hln);

    // 14: FF1 + exact GELU
    sgemm_kernel<2><<<dim3(16, 32), blk>>>(hln, ff1_w, ff1_b, nullptr, ff1, 4096, 2048, 1024);

    // 15: FF2 + residual -> output
    sgemm_kernel<1><<<dim3(8, 32), blk>>>(ff1, ff2_w, ff2_b, out1, out, 4096, 1024, 2048);
}

// round 14
// speedup vs baseline: 1.3705x; 1.3705x over previous
#include <cuda_runtime.h>
#include <cuda_bf16.h>
#include <math.h>
#include <stdint.h>

// Problem constants
#define B_  4
#define N_  1024
#define M_  2048
#define D_  1024
#define H_  16
#define HD_ 64
#define P_  64

// ---------------------------------------------------------------------------
// Scratch
// ---------------------------------------------------------------------------
// fp32 scratch (floats)
#define OFF_Q     0ull
#define OFF_K     4194304ull
#define OFF_V     12582912ull
#define OFF_GEOQ  20971520ull
#define OFF_GEOK  21233664ull
#define OFF_BIAS  21757952ull
#define OFF_OUT1  30146560ull
#define F32_TOTAL 34340864ull
__device__ __align__(256) float g_f32[F32_TOTAL];

// bf16 scratch: every tensor stored as hi/lo pair, lo at offset +elems.
#define BF_WQT   0ull          // 1048576 x2
#define BF_WKT   2097152ull
#define BF_WVT   4194304ull
#define BF_WOT   6291456ull
#define BF_FF1T  8388608ull    // 2097152 x2
#define BF_FF2T  12582912ull   // 2097152 x2
#define BF_GQT   16777216ull   // 65536 x2
#define BF_GKT   16908288ull
#define BF_QIN   17039360ull   // 4194304 x2
#define BF_KVIN  25427968ull   // 8388608 x2
#define BF_ATTN  42205184ull   // 4194304 x2
#define BF_HLN   50593792ull   // 4194304 x2
#define BF_FF1O  58982400ull   // 8388608 x2
#define BF_TOTAL 75759616ull
__device__ __align__(256) __nv_bfloat16 g_bf[BF_TOTAL];

// ---------------------------------------------------------------------------
// Helpers
// ---------------------------------------------------------------------------
__device__ __forceinline__ uint32_t smem_u32(const void* p) {
    uint32_t a;
    asm("{ .reg .u64 t; cvta.to.shared.u64 t, %1; cvt.u32.u64 %0, t; }" : "=r"(a) : "l"(p));
    return a;
}

#define LDSM_X4(r0, r1, r2, r3, addr) \
    asm volatile("ldmatrix.sync.aligned.m8n8.x4.shared.b16 {%0,%1,%2,%3}, [%4];" \
                 : "=r"(r0), "=r"(r1), "=r"(r2), "=r"(r3) : "r"(addr))

#define MMA_BF16(d, a, b0, b1) \
    asm volatile("mma.sync.aligned.m16n8k16.row.col.f32.bf16.bf16.f32 " \
                 "{%0,%1,%2,%3}, {%4,%5,%6,%7}, {%8,%9}, {%0,%1,%2,%3};" \
                 : "+f"((d)[0]), "+f"((d)[1]), "+f"((d)[2]), "+f"((d)[3]) \
                 : "r"((a)[0]), "r"((a)[1]), "r"((a)[2]), "r"((a)[3]), \
                   "r"(b0), "r"(b1))

#define CP_ASYNC_16(dst, src) \
    asm volatile("cp.async.cg.shared.global [%0], [%1], 16;" :: "r"(dst), "l"(src))
#define CP_ASYNC_16Z(dst, src, vsz) \
    asm volatile("cp.async.cg.shared.global [%0], [%1], 16, %2;" :: "r"(dst), "l"(src), "r"(vsz))
#define CP_COMMIT() asm volatile("cp.async.commit_group;" ::: "memory")
#define CP_WAIT(n)  asm volatile("cp.async.wait_group %0;" :: "n"(n) : "memory")

__device__ __forceinline__ void split_bf16(float v, __nv_bfloat16& hi, __nv_bfloat16& lo) {
    hi = __float2bfloat16(v);
    lo = __float2bfloat16(v - __bfloat162float(hi));
}

// ---------------------------------------------------------------------------
// Weight transpose + fp32 -> bf16 hi/lo split: Wt[n,k] pair = W[k,n]
// ---------------------------------------------------------------------------
__global__ void transpose_bf16_kernel(const float* __restrict__ W,
                                      __nv_bfloat16* __restrict__ Wt, int K, int Nc,
                                      size_t elems)
{
    __shared__ float t[32][33];
    int x = blockIdx.x * 32 + threadIdx.x;
    int y0 = blockIdx.y * 32;
    #pragma unroll
    for (int j = 0; j < 32; j += 8)
        t[threadIdx.y + j][threadIdx.x] = W[(size_t)(y0 + threadIdx.y + j) * Nc + x];
    __syncthreads();
    int k = y0 + threadIdx.x;
    int n0 = blockIdx.x * 32;
    #pragma unroll
    for (int j = 0; j < 32; j += 8) {
        float v = t[threadIdx.x][threadIdx.y + j];
        __nv_bfloat16 hi, lo;
        split_bf16(v, hi, lo);
        size_t idx = (size_t)(n0 + threadIdx.y + j) * K + k;
        Wt[idx] = hi;
        Wt[idx + elems] = lo;
    }
}

// ---------------------------------------------------------------------------
// LayerNorm (fp32 in, bf16 hi/lo out), one block (256 thr) per row of D=1024
// ---------------------------------------------------------------------------
__global__ void layernorm_bf16_kernel(const float* __restrict__ x,
                                      const float* __restrict__ g,
                                      const float* __restrict__ bta,
                                      __nv_bfloat16* __restrict__ y,
                                      size_t elems)
{
    int row = blockIdx.x;
    int t = threadIdx.x;
    float4 v = reinterpret_cast<const float4*>(x + (size_t)row * D_)[t];
    float s  = v.x + v.y + v.z + v.w;
    float ss = v.x*v.x + v.y*v.y + v.z*v.z + v.w*v.w;

    __shared__ float sh[16];
    int lane = t & 31, wid = t >> 5;
    #pragma unroll
    for (int o = 16; o; o >>= 1) {
        s  += __shfl_xor_sync(0xffffffffu, s,  o);
        ss += __shfl_xor_sync(0xffffffffu, ss, o);
    }
    if (lane == 0) { sh[wid] = s; sh[8 + wid] = ss; }
    __syncthreads();
    if (t < 32) {
        s  = (t < 8) ? sh[t]     : 0.f;
        ss = (t < 8) ? sh[8 + t] : 0.f;
        #pragma unroll
        for (int o = 4; o; o >>= 1) {
            s  += __shfl_xor_sync(0xffffffffu, s,  o);
            ss += __shfl_xor_sync(0xffffffffu, ss, o);
        }
        if (t == 0) { sh[0] = s; sh[8] = ss; }
    }
    __syncthreads();
    float mean = sh[0] * (1.f / D_);
    float var  = sh[8] * (1.f / D_) - mean * mean;
    float rstd = rsqrtf(var + 1e-5f);

    float4 gv = reinterpret_cast<const float4*>(g)[t];
    float4 bv = reinterpret_cast<const float4*>(bta)[t];
    float o[4];
    o[0] = (v.x - mean) * rstd * gv.x + bv.x;
    o[1] = (v.y - mean) * rstd * gv.y + bv.y;
    o[2] = (v.z - mean) * rstd * gv.z + bv.z;
    o[3] = (v.w - mean) * rstd * gv.w + bv.w;

    __nv_bfloat16 hi[4], lo[4];
    #pragma unroll
    for (int i = 0; i < 4; i++) split_bf16(o[i], hi[i], lo[i]);

    size_t base = (size_t)row * D_ + t * 4;
    uint2 uh, ul;
    __nv_bfloat162 h01 = __halves2bfloat162(hi[0], hi[1]);
    __nv_bfloat162 h23 = __halves2bfloat162(hi[2], hi[3]);
    __nv_bfloat162 l01 = __halves2bfloat162(lo[0], lo[1]);
    __nv_bfloat162 l23 = __halves2bfloat162(lo[2], lo[3]);
    uh.x = *reinterpret_cast<uint32_t*>(&h01);
    uh.y = *reinterpret_cast<uint32_t*>(&h23);
    ul.x = *reinterpret_cast<uint32_t*>(&l01);
    ul.y = *reinterpret_cast<uint32_t*>(&l23);
    *reinterpret_cast<uint2*>(y + base) = uh;
    *reinterpret_cast<uint2*>(y + elems + base) = ul;
}

// ---------------------------------------------------------------------------
// bf16x3 split-precision HMMA GEMM:
// C[Mr,Nc] = (Ahi+Alo)[Mr,K] @ (Whi+Wlo)[Nc,K]^T + bias  (lo*lo dropped)
// Tile 128x128, BK=32, 4-stage cp.async pipeline, 8 warps (4x2), warp 32x64.
// smem rows padded to 40 bf16. EPI: 0=+bias, 1=+bias+R, 2=+bias+GELU.
// OUTBF16: write bf16 hi/lo pair (lo at Cout + c_elems).
// ---------------------------------------------------------------------------
#define HB_LDS   40
#define HB_STAGE (128 * HB_LDS)                 // bf16 elems per matrix stage
#define HB_SMEM  (16 * HB_STAGE * 2)            // 4 stages * 4 matrices * 2B = 163840

template<int EPI, int OUTBF16>
__global__ __launch_bounds__(256, 1)
void hmma_gemm_kernel(const __nv_bfloat16* __restrict__ Ah,
                      const __nv_bfloat16* __restrict__ Al,
                      const __nv_bfloat16* __restrict__ Wh,
                      const __nv_bfloat16* __restrict__ Wl,
                      const float* __restrict__ bias,
                      const float* __restrict__ R,
                      void* __restrict__ Cout, int K, int Nc, size_t c_elems)
{
    extern __shared__ __nv_bfloat16 smem[];
    __nv_bfloat16* sAh = smem;                   // [4][128*40]
    __nv_bfloat16* sAl = smem + 4 * HB_STAGE;
    __nv_bfloat16* sBh = smem + 8 * HB_STAGE;
    __nv_bfloat16* sBl = smem + 12 * HB_STAGE;

    const int tid = threadIdx.x;
    const int wid = tid >> 5, lane = tid & 31;
    const int wm = wid & 3, wn = wid >> 2;       // 4x2 warp grid
    const int row0 = blockIdx.y * 128, col0 = blockIdx.x * 128;
    const int KT = K >> 5;                       // BK=32 chunks

    float acc[2][8][4] = {};

    // stage loader: 128 rows x 32 bf16 per matrix; 512 16B txns = 2 iters
    auto load_stage = [&](int kt) {
        int s = kt & 3;
        int k0 = kt << 5;
        uint32_t dAh = smem_u32(sAh + s * HB_STAGE);
        uint32_t dAl = smem_u32(sAl + s * HB_STAGE);
        uint32_t dBh = smem_u32(sBh + s * HB_STAGE);
        uint32_t dBl = smem_u32(sBl + s * HB_STAGE);
        #pragma unroll
        for (int i = 0; i < 2; i++) {
            int idx = i * 256 + tid;             // 0..511
            int r = idx >> 2, c = idx & 3;       // r: 0..127, c: 0..3
            uint32_t off = (uint32_t)(r * HB_LDS + c * 8) * 2;
            size_t ga = (size_t)(row0 + r) * K + k0 + c * 8;
            CP_ASYNC_16(dAh + off, Ah + ga);
            CP_ASYNC_16(dAl + off, Al + ga);
            size_t gb = (size_t)(col0 + r) * K + k0 + c * 8;
            int vsz = (col0 + r < Nc) ? 16 : 0;
            CP_ASYNC_16Z(dBh + off, Wh + gb, vsz);
            CP_ASYNC_16Z(dBl + off, Wl + gb, vsz);
        }
        CP_COMMIT();
    };

    load_stage(0);
    load_stage(1);
    load_stage(2);

    const int rA = (lane & 15);
    const int cH = (lane >> 4) * 16;             // 16B column half select

    for (int kt = 0; kt < KT; kt++) {
        CP_WAIT(2);
        __syncthreads();

        if (kt + 3 < KT) load_stage(kt + 3);
        else CP_COMMIT();                        // keep group count advancing

        int s = kt & 3;
        uint32_t baseAh = smem_u32(sAh + s * HB_STAGE);
        uint32_t baseAl = smem_u32(sAl + s * HB_STAGE);
        uint32_t baseBh = smem_u32(sBh + s * HB_STAGE);
        uint32_t baseBl = smem_u32(sBl + s * HB_STAGE);

        #pragma unroll
        for (int ks = 0; ks < 2; ks++) {
            uint32_t ah[2][4], al[2][4], bh[4][4], bl[4][4];
            #pragma unroll
            for (int mh = 0; mh < 2; mh++) {
                uint32_t o = (uint32_t)((wm * 32 + mh * 16 + rA) * HB_LDS + ks * 16) * 2 + cH;
                LDSM_X4(ah[mh][0], ah[mh][1], ah[mh][2], ah[mh][3], baseAh + o);
                LDSM_X4(al[mh][0], al[mh][1], al[mh][2], al[mh][3], baseAl + o);
            }
            #pragma unroll
            for (int np = 0; np < 4; np++) {
                uint32_t o = (uint32_t)((wn * 64 + np * 16 + rA) * HB_LDS + ks * 16) * 2 + cH;
                LDSM_X4(bh[np][0], bh[np][1], bh[np][2], bh[np][3], baseBh + o);
                LDSM_X4(bl[np][0], bl[np][1], bl[np][2], bl[np][3], baseBl + o);
            }
            #pragma unroll
            for (int mh = 0; mh < 2; mh++)
                #pragma unroll
                for (int ni = 0; ni < 8; ni++) {
                    int np = ni >> 1, h = ni & 1;
                    MMA_BF16(acc[mh][ni], ah[mh], bh[np][h], bh[np][h + 2]);
                    MMA_BF16(acc[mh][ni], ah[mh], bl[np][h], bl[np][h + 2]);
                    MMA_BF16(acc[mh][ni], al[mh], bh[np][h], bh[np][h + 2]);
                }
        }
    }

    // Epilogue: registers -> global, fused bias / residual / GELU
    const int lr = lane >> 2;                    // 0..7
    const int lc = (lane & 3) * 2;               // 0,2,4,6
    #pragma unroll
    for (int mh = 0; mh < 2; mh++) {
        #pragma unroll
        for (int ni = 0; ni < 8; ni++) {
            int cc = col0 + wn * 64 + ni * 8 + lc;
            if (cc >= Nc) continue;
            float b0 = __ldg(bias + cc), b1 = __ldg(bias + cc + 1);
            #pragma unroll
            for (int rh = 0; rh < 2; rh++) {
                int rr = row0 + wm * 32 + mh * 16 + rh * 8 + lr;
                float x0 = acc[mh][ni][rh * 2 + 0] + b0;
                float x1 = acc[mh][ni][rh * 2 + 1] + b1;
                size_t gidx = (size_t)rr * Nc + cc;
                if (EPI == 1) {
                    float2 rv = *reinterpret_cast<const float2*>(R + gidx);
                    x0 += rv.x; x1 += rv.y;
                } else if (EPI == 2) {
                    x0 = 0.5f * x0 * (1.f + erff(x0 * 0.70710678118654752f));
                    x1 = 0.5f * x1 * (1.f + erff(x1 * 0.70710678118654752f));
                }
                if (OUTBF16) {
                    __nv_bfloat16 h0, l0, h1, l1;
                    split_bf16(x0, h0, l0);
                    split_bf16(x1, h1, l1);
                    __nv_bfloat162 ph = __halves2bfloat162(h0, h1);
                    __nv_bfloat162 pl = __halves2bfloat162(l0, l1);
                    *reinterpret_cast<uint32_t*>((__nv_bfloat16*)Cout + gidx) =
                        *reinterpret_cast<uint32_t*>(&ph);
                    *reinterpret_cast<uint32_t*>((__nv_bfloat16*)Cout + c_elems + gidx) =
                        *reinterpret_cast<uint32_t*>(&pl);
                } else {
                    *reinterpret_cast<float2*>((float*)Cout + gidx) = make_float2(x0, x1);
                }
            }
        }
    }
}

// ---------------------------------------------------------------------------
// L2 normalize over sequence axis: x[B, Nn, 64]; one block per (b, p).
// ---------------------------------------------------------------------------
__global__ void l2norm_kernel(float* __restrict__ x, int Nn)
{
    int b = blockIdx.x >> 6;
    int p = blockIdx.x & 63;
    float* base = x + (size_t)b * Nn * P_ + p;
    int t = threadIdx.x;

    float ss = 0.f;
    for (int n = t; n < Nn; n += 256) {
        float v = base[(size_t)n * P_];
        ss += v * v;
    }
    __shared__ float sh[9];
    int lane = t & 31, wid = t >> 5;
    #pragma unroll
    for (int o = 16; o; o >>= 1) ss += __shfl_xor_sync(0xffffffffu, ss, o);
    if (lane == 0) sh[wid] = ss;
    __syncthreads();
    if (t == 0) {
        float tot = 0.f;
        #pragma unroll
        for (int i = 0; i < 8; i++) tot += sh[i];
        sh[8] = 1.f / fmaxf(sqrtf(tot), 1e-12f);
    }
    __syncthreads();
    float inv = sh[8];
    for (int n = t; n < Nn; n += 256) base[(size_t)n * P_] *= inv;
}

// ---------------------------------------------------------------------------
// Geo bias: bias[b,n,m] = f(geo_q . geo_k), f = relu*pos - relu(-)*neg
// ---------------------------------------------------------------------------
__global__ void bias_nt_kernel(const float* __restrict__ gq, const float* __restrict__ gk,
                               const float* __restrict__ pos, const float* __restrict__ neg,
                               float* __restrict__ Cb)
{
    __shared__ float Aq[64 * 68];
    __shared__ float Bk[64 * 68];
    int tid = threadIdx.x;
    int m0 = blockIdx.x * 64, n0 = blockIdx.y * 64, b = blockIdx.z;

    #pragma unroll
    for (int it = 0; it < 4; it++) {
        int idx = tid + it * 256;
        int row = idx >> 4;
        int c4  = (idx & 15) * 4;
        *reinterpret_cast<float4*>(&Aq[row * 68 + c4]) =
            *reinterpret_cast<const float4*>(&gq[((size_t)(b * N_ + n0 + row)) * P_ + c4]);
        *reinterpret_cast<float4*>(&Bk[row * 68 + c4]) =
            *reinterpret_cast<const float4*>(&gk[((size_t)(b * M_ + m0 + row)) * P_ + c4]);
    }
    __syncthreads();

    int ty = tid >> 4, tx = tid & 15;
    float acc[4][4] = {};
    #pragma unroll
    for (int k = 0; k < 64; k += 4) {
        float4 a[4], kb[4];
        #pragma unroll
        for (int i = 0; i < 4; i++) a[i]  = *reinterpret_cast<float4*>(&Aq[(ty*4 + i)*68 + k]);
        #pragma unroll
        for (int j = 0; j < 4; j++) kb[j] = *reinterpret_cast<float4*>(&Bk[(tx*4 + j)*68 + k]);
        #pragma unroll
        for (int i = 0; i < 4; i++)
            #pragma unroll
            for (int j = 0; j < 4; j++)
                acc[i][j] += a[i].x*kb[j].x + a[i].y*kb[j].y + a[i].z*kb[j].z + a[i].w*kb[j].w;
    }

    float ps = pos[0], ns = neg[0];
    #pragma unroll
    for (int i = 0; i < 4; i++) {
        float4 o;
        o.x = acc[i][0] > 0.f ? acc[i][0] * ps : acc[i][0] * ns;
        o.y = acc[i][1] > 0.f ? acc[i][1] * ps : acc[i][1] * ns;
        o.z = acc[i][2] > 0.f ? acc[i][2] * ps : acc[i][2] * ns;
        o.w = acc[i][3] > 0.f ? acc[i][3] * ps : acc[i][3] * ns;
        *reinterpret_cast<float4*>(
            &Cb[((size_t)(b * N_ + n0 + ty*4 + i)) * M_ + m0 + tx*4]) = o;
    }
}

// ---------------------------------------------------------------------------
// Flash attention with additive bias (fp32 math, bf16 hi/lo out for wo GEMM)
// ---------------------------------------------------------------------------
#define FL_STRIDE 68
#define FLASH_SMEM (4 * 64 * FL_STRIDE * 4)
#define ATTN_ELEMS 4194304ull

__global__ void flash_attn_kernel(const float* __restrict__ Q, const float* __restrict__ K,
                                  const float* __restrict__ V, const float* __restrict__ Bias,
                                  const float* __restrict__ logit_scale,
                                  __nv_bfloat16* __restrict__ O)
{
    extern __shared__ float sm[];
    float* Qs = sm;
    float* Ks = Qs + 64 * FL_STRIDE;
    float* Vs = Ks + 64 * FL_STRIDE;
    float* Ps = Vs + 64 * FL_STRIDE;

    const int tid = threadIdx.x;
    const int n0 = blockIdx.x * 64;
    const int h  = blockIdx.y;
    const int b  = blockIdx.z;
    const float scale = __expf(logit_scale[0]) * 0.125f;

    #pragma unroll
    for (int it = 0; it < 4; it++) {
        int idx = tid + it * 256;
        int row = idx >> 4;
        int c4  = (idx & 15) * 4;
        float4 v = *reinterpret_cast<const float4*>(
            &Q[((size_t)(b * N_ + n0 + row)) * D_ + h * HD_ + c4]);
        v.x *= scale; v.y *= scale; v.z *= scale; v.w *= scale;
        *reinterpret_cast<float4*>(&Qs[row * FL_STRIDE + c4]) = v;
    }

    const int r  = tid >> 2;
    const int cg = tid & 3;
    const int ty = tid >> 4, tx = tid & 15;

    float Oacc[16] = {};
    float m_i = -1e30f, l_i = 0.f;

    for (int m0 = 0; m0 < M_; m0 += 64) {
        __syncthreads();
        #pragma unroll
        for (int it = 0; it < 4; it++) {
            int idx = tid + it * 256;
            int row = idx >> 4;
            int c4  = (idx & 15) * 4;
            size_t gbase = ((size_t)(b * M_ + m0 + row)) * D_ + h * HD_ + c4;
            *reinterpret_cast<float4*>(&Ks[row * FL_STRIDE + c4]) =
                *reinterpret_cast<const float4*>(&K[gbase]);
            *reinterpret_cast<float4*>(&Vs[row * FL_STRIDE + c4]) =
                *reinterpret_cast<const float4*>(&V[gbase]);
        }
        __syncthreads();

        float acc[4][4] = {};
        #pragma unroll
        for (int k = 0; k < 64; k += 4) {
            float4 qa[4], kb[4];
            #pragma unroll
            for (int i = 0; i < 4; i++) qa[i] = *reinterpret_cast<float4*>(&Qs[(ty*4+i)*FL_STRIDE + k]);
            #pragma unroll
            for (int j = 0; j < 4; j++) kb[j] = *reinterpret_cast<float4*>(&Ks[(tx*4+j)*FL_STRIDE + k]);
            #pragma unroll
            for (int i = 0; i < 4; i++)
                #pragma unroll
                for (int j = 0; j < 4; j++)
                    acc[i][j] += qa[i].x*kb[j].x + qa[i].y*kb[j].y +
                                 qa[i].z*kb[j].z + qa[i].w*kb[j].w;
        }
        #pragma unroll
        for (int i = 0; i < 4; i++) {
            float4 bv = *reinterpret_cast<const float4*>(
                &Bias[((size_t)(b * N_ + n0 + ty*4 + i)) * M_ + m0 + tx*4]);
            float* prow = &Ps[(ty*4 + i) * FL_STRIDE + tx*4];
            prow[0] = acc[i][0] + bv.x;
            prow[1] = acc[i][1] + bv.y;
            prow[2] = acc[i][2] + bv.z;
            prow[3] = acc[i][3] + bv.w;
        }
        __syncthreads();

        float s[16];
        float cmax = -1e30f;
        #pragma unroll
        for (int jj = 0; jj < 16; jj++) {
            s[jj] = Ps[r * FL_STRIDE + cg * 16 + jj];
            cmax = fmaxf(cmax, s[jj]);
        }
        cmax = fmaxf(cmax, __shfl_xor_sync(0xffffffffu, cmax, 1));
        cmax = fmaxf(cmax, __shfl_xor_sync(0xffffffffu, cmax, 2));
        float m_new = fmaxf(m_i, cmax);
        float alpha = __expf(m_i - m_new);
        float lsum = 0.f;
        #pragma unroll
        for (int jj = 0; jj < 16; jj++) {
            float p = __expf(s[jj] - m_new);
            Ps[r * FL_STRIDE + cg * 16 + jj] = p;
            lsum += p;
        }
        lsum += __shfl_xor_sync(0xffffffffu, lsum, 1);
        lsum += __shfl_xor_sync(0xffffffffu, lsum, 2);
        l_i = l_i * alpha + lsum;
        m_i = m_new;
        __syncthreads();

        #pragma unroll
        for (int dd = 0; dd < 16; dd++) Oacc[dd] *= alpha;
        #pragma unroll 4
        for (int j = 0; j < 64; j++) {
            float p = Ps[r * FL_STRIDE + j];
            const float* vrow = &Vs[j * FL_STRIDE + cg * 16];
            float4 v0 = *reinterpret_cast<const float4*>(vrow + 0);
            float4 v1 = *reinterpret_cast<const float4*>(vrow + 4);
            float4 v2 = *reinterpret_cast<const float4*>(vrow + 8);
            float4 v3 = *reinterpret_cast<const float4*>(vrow + 12);
            Oacc[0]  += p * v0.x; Oacc[1]  += p * v0.y; Oacc[2]  += p * v0.z; Oacc[3]  += p * v0.w;
            Oacc[4]  += p * v1.x; Oacc[5]  += p * v1.y; Oacc[6]  += p * v1.z; Oacc[7]  += p * v1.w;
            Oacc[8]  += p * v2.x; Oacc[9]  += p * v2.y; Oacc[10] += p * v2.z; Oacc[11] += p * v2.w;
            Oacc[12] += p * v3.x; Oacc[13] += p * v3.y; Oacc[14] += p * v3.z; Oacc[15] += p * v3.w;
        }
    }

    float inv = 1.f / l_i;
    size_t obase = ((size_t)(b * N_ + n0 + r)) * D_ + h * HD_ + cg * 16;
    uint32_t ph[8], pl[8];
    #pragma unroll
    for (int i = 0; i < 8; i++) {
        float v0 = Oacc[2*i] * inv, v1 = Oacc[2*i+1] * inv;
        __nv_bfloat16 h0, l0, h1, l1;
        split_bf16(v0, h0, l0);
        split_bf16(v1, h1, l1);
        __nv_bfloat162 hh = __halves2bfloat162(h0, h1);
        __nv_bfloat162 ll = __halves2bfloat162(l0, l1);
        ph[i] = *reinterpret_cast<uint32_t*>(&hh);
        pl[i] = *reinterpret_cast<uint32_t*>(&ll);
    }
    *reinterpret_cast<uint4*>(O + obase)     = make_uint4(ph[0], ph[1], ph[2], ph[3]);
    *reinterpret_cast<uint4*>(O + obase + 8) = make_uint4(ph[4], ph[5], ph[6], ph[7]);
    *reinterpret_cast<uint4*>(O + ATTN_ELEMS + obase)     = make_uint4(pl[0], pl[1], pl[2], pl[3]);
    *reinterpret_cast<uint4*>(O + ATTN_ELEMS + obase + 8) = make_uint4(pl[4], pl[5], pl[6], pl[7]);
}

// ---------------------------------------------------------------------------
// Launcher
// ---------------------------------------------------------------------------
extern "C" void kernel_launch(void* const* d_in, const int* in_sizes, int n_in,
                              void* d_out, int out_size)
{
    const float* dataset  = (const float*)d_in[0];
    const float* visual   = (const float*)d_in[1];
    const float* wq_w     = (const float*)d_in[2];
    const float* wq_b     = (const float*)d_in[3];
    const float* wk_w     = (const float*)d_in[4];
    const float* wk_b     = (const float*)d_in[5];
    const float* wv_w     = (const float*)d_in[6];
    const float* wv_b     = (const float*)d_in[7];
    const float* wo_w     = (const float*)d_in[8];
    const float* wo_b     = (const float*)d_in[9];
    const float* gq_w     = (const float*)d_in[10];
    const float* gq_b     = (const float*)d_in[11];
    const float* gk_w     = (const float*)d_in[12];
    const float* gk_b     = (const float*)d_in[13];
    const float* pos_s    = (const float*)d_in[14];
    const float* neg_s    = (const float*)d_in[15];
    const float* attn_ls  = (const float*)d_in[16];
    const float* ln_q_g   = (const float*)d_in[17];
    const float* ln_q_b   = (const float*)d_in[18];
    const float* ln_kv_g  = (const float*)d_in[19];
    const float* ln_kv_b  = (const float*)d_in[20];
    const float* ln_out_g = (const float*)d_in[21];
    const float* ln_out_b = (const float*)d_in[22];
    const float* ff1_w    = (const float*)d_in[23];
    const float* ff1_b    = (const float*)d_in[24];
    const float* ff2_w    = (const float*)d_in[25];
    const float* ff2_b    = (const float*)d_in[26];
    float* out = (float*)d_out;

    float* sf = nullptr;
    __nv_bfloat16* bf = nullptr;
    cudaGetSymbolAddress((void**)&sf, g_f32);
    cudaGetSymbolAddress((void**)&bf, g_bf);

    float* Qp    = sf + OFF_Q;
    float* Kp    = sf + OFF_K;
    float* Vp    = sf + OFF_V;
    float* geoq  = sf + OFF_GEOQ;
    float* geok  = sf + OFF_GEOK;
    float* biasb = sf + OFF_BIAS;
    float* out1  = sf + OFF_OUT1;

    __nv_bfloat16* wqT  = bf + BF_WQT;
    __nv_bfloat16* wkT  = bf + BF_WKT;
    __nv_bfloat16* wvT  = bf + BF_WVT;
    __nv_bfloat16* woT  = bf + BF_WOT;
    __nv_bfloat16* ff1T = bf + BF_FF1T;
    __nv_bfloat16* ff2T = bf + BF_FF2T;
    __nv_bfloat16* gqT  = bf + BF_GQT;
    __nv_bfloat16* gkT  = bf + BF_GKT;
    __nv_bfloat16* qinb = bf + BF_QIN;
    __nv_bfloat16* kvinb= bf + BF_KVIN;
    __nv_bfloat16* attnb= bf + BF_ATTN;
    __nv_bfloat16* hlnb = bf + BF_HLN;
    __nv_bfloat16* ff1ob= bf + BF_FF1O;

    cudaFuncSetAttribute(hmma_gemm_kernel<0,0>, cudaFuncAttributeMaxDynamicSharedMemorySize, HB_SMEM);
    cudaFuncSetAttribute(hmma_gemm_kernel<1,0>, cudaFuncAttributeMaxDynamicSharedMemorySize, HB_SMEM);
    cudaFuncSetAttribute(hmma_gemm_kernel<2,1>, cudaFuncAttributeMaxDynamicSharedMemorySize, HB_SMEM);
    cudaFuncSetAttribute(flash_attn_kernel, cudaFuncAttributeMaxDynamicSharedMemorySize, FLASH_SMEM);

    dim3 blk(256);
    dim3 tb(32, 8);

    // Weight transposes (fp32 -> bf16 hi/lo, [K,Nc] -> [Nc,K])
    transpose_bf16_kernel<<<dim3(32, 32), tb>>>(wq_w,  wqT,  1024, 1024, 1048576ull);
    transpose_bf16_kernel<<<dim3(32, 32), tb>>>(wk_w,  wkT,  1024, 1024, 1048576ull);
    transpose_bf16_kernel<<<dim3(32, 32), tb>>>(wv_w,  wvT,  1024, 1024, 1048576ull);
    transpose_bf16_kernel<<<dim3(32, 32), tb>>>(wo_w,  woT,  1024, 1024, 1048576ull);
    transpose_bf16_kernel<<<dim3(64, 32), tb>>>(ff1_w, ff1T, 1024, 2048, 2097152ull);
    transpose_bf16_kernel<<<dim3(32, 64), tb>>>(ff2_w, ff2T, 2048, 1024, 2097152ull);
    transpose_bf16_kernel<<<dim3(2,  32), tb>>>(gq_w,  gqT,  1024, 64, 65536ull);
    transpose_bf16_kernel<<<dim3(2,  32), tb>>>(gk_w,  gkT,  1024, 64, 65536ull);

    // LayerNorms (bf16 hi/lo outputs feed GEMM A)
    layernorm_bf16_kernel<<<4096, blk>>>(dataset, ln_q_g, ln_q_b, qinb, 4194304ull);
    layernorm_bf16_kernel<<<8192, blk>>>(visual, ln_kv_g, ln_kv_b, kvinb, 8388608ull);

    // Geo projections (Nc=64, fp32 out)
    hmma_gemm_kernel<0,0><<<dim3(1, 32), blk, HB_SMEM>>>(
        qinb, qinb + 4194304, gqT, gqT + 65536, gq_b, nullptr, geoq, 1024, 64, 0);
    hmma_gemm_kernel<0,0><<<dim3(1, 64), blk, HB_SMEM>>>(
        kvinb, kvinb + 8388608, gkT, gkT + 65536, gk_b, nullptr, geok, 1024, 64, 0);

    l2norm_kernel<<<256, blk>>>(geoq, N_);
    l2norm_kernel<<<256, blk>>>(geok, M_);

    bias_nt_kernel<<<dim3(32, 16, 4), blk>>>(geoq, geok, pos_s, neg_s, biasb);

    // QKV projections (fp32 out)
    hmma_gemm_kernel<0,0><<<dim3(8, 32), blk, HB_SMEM>>>(
        qinb, qinb + 4194304, wqT, wqT + 1048576, wq_b, nullptr, Qp, 1024, 1024, 0);
    hmma_gemm_kernel<0,0><<<dim3(8, 64), blk, HB_SMEM>>>(
        kvinb, kvinb + 8388608, wkT, wkT + 1048576, wk_b, nullptr, Kp, 1024, 1024, 0);
    hmma_gemm_kernel<0,0><<<dim3(8, 64), blk, HB_SMEM>>>(
        kvinb, kvinb + 8388608, wvT, wvT + 1048576, wv_b, nullptr, Vp, 1024, 1024, 0);

    // Flash attention (bf16 hi/lo output)
    flash_attn_kernel<<<dim3(16, 16, 4), blk, FLASH_SMEM>>>(Qp, Kp, Vp, biasb, attn_ls, attnb);

    // Output projection + residual (fp32 out)
    hmma_gemm_kernel<1,0><<<dim3(8, 32), blk, HB_SMEM>>>(
        attnb, attnb + 4194304, woT, woT + 1048576, wo_b, dataset, out1, 1024, 1024, 0);

    // Post-LN (bf16 hi/lo out)
    layernorm_bf16_kernel<<<4096, blk>>>(out1, ln_out_g, ln_out_b, hlnb, 4194304ull);

    // FF1 + GELU (bf16 hi/lo out)
    hmma_gemm_kernel<2,1><<<dim3(16, 32), blk, HB_SMEM>>>(
        hlnb, hlnb + 4194304, ff1T, ff1T + 2097152, ff1_b, nullptr, ff1ob, 1024, 2048, 8388608ull);

    // FF2 + residual -> output (fp32)
    hmma_gemm_kernel<1,0><<<dim3(8, 32), blk, HB_SMEM>>>(
        ff1ob, ff1ob + 8388608, ff2T, ff2T + 2097152, ff2_b, out1, out, 2048, 1024, 0);
}